// round 1
// baseline (speedup 1.0000x reference)
#include <cuda_runtime.h>
#include <cuda_bf16.h>

// Problem constants: B=8, N=2048, D=DQ=DV=1024
#define BATCH 8
#define SEQ   2048
#define DIM   1024
#define ROWS  (BATCH * SEQ)        // 16384

// Scratch (static __device__ — no allocation allowed in kernel_launch)
__device__ float g_Q[(size_t)ROWS * DIM];          // 64 MB
__device__ float g_K[(size_t)ROWS * DIM];          // 64 MB
__device__ float g_V[(size_t)ROWS * DIM];          // 64 MB
__device__ float g_S[(size_t)BATCH * SEQ * SEQ];   // 128 MB

// ---------------------------------------------------------------------------
// Tiled fp32 GEMM: C[M,N] = A[M,K] * op(B) (+ bias), 128x128 tile, K-step 16,
// 256 threads, 8x8 accumulators per thread. All dims here are multiples of
// the tile sizes (M,N % 128 == 0, K % 16 == 0) so no bounds checks.
//   TRANSB=0: B is [K,N] row-major (projections, P@V)
//   TRANSB=1: B is [N,K] row-major (Q @ K^T)
// blockIdx.z batches with the given strides.
// ---------------------------------------------------------------------------
template<bool TRANSB, bool HASBIAS>
__global__ __launch_bounds__(256, 2)
void gemm_kernel(const float* __restrict__ Ag, const float* __restrict__ Bg,
                 const float* __restrict__ bias, float* __restrict__ Cg,
                 int M, int N, int K,
                 long long strideA, long long strideB, long long strideC)
{
    __shared__ float As[16][132];
    __shared__ float Bs[16][132];

    const float* A = Ag + (long long)blockIdx.z * strideA;
    const float* B = Bg + (long long)blockIdx.z * strideB;
    float*       C = Cg + (long long)blockIdx.z * strideC;

    const int tid = threadIdx.x;
    const int tx  = tid & 15;         // 0..15  -> 8 cols each
    const int ty  = tid >> 4;         // 0..15  -> 8 rows each
    const int rowBase = blockIdx.y * 128;
    const int colBase = blockIdx.x * 128;

    float acc[8][8];
#pragma unroll
    for (int i = 0; i < 8; ++i)
#pragma unroll
        for (int j = 0; j < 8; ++j) acc[i][j] = 0.0f;

    // loader indices (K-major tiles stored transposed: s[kk][row])
    const int lr    = tid & 127;          // row within 128-row tile
    const int kbase = (tid >> 7) * 8;     // 0 or 8

    // non-trans B loader indices
    const int bkk = tid >> 4;             // 0..15
    const int bc  = (tid & 15) * 8;       // col quad base

    for (int k0 = 0; k0 < K; k0 += 16) {
        // ---- load A tile (always [rows,K] row-major, transpose into As)
#pragma unroll
        for (int u = 0; u < 2; ++u) {
            int kq = kbase + u * 4;
            float4 v = *(const float4*)(A + (long long)(rowBase + lr) * K + k0 + kq);
            As[kq + 0][lr] = v.x; As[kq + 1][lr] = v.y;
            As[kq + 2][lr] = v.z; As[kq + 3][lr] = v.w;
        }
        // ---- load B tile
        if (TRANSB) {
#pragma unroll
            for (int u = 0; u < 2; ++u) {
                int kq = kbase + u * 4;
                float4 v = *(const float4*)(B + (long long)(colBase + lr) * K + k0 + kq);
                Bs[kq + 0][lr] = v.x; Bs[kq + 1][lr] = v.y;
                Bs[kq + 2][lr] = v.z; Bs[kq + 3][lr] = v.w;
            }
        } else {
            const float* bp = B + (long long)(k0 + bkk) * N + colBase + bc;
            float4 v0 = *(const float4*)(bp);
            float4 v1 = *(const float4*)(bp + 4);
            *(float4*)&Bs[bkk][bc]     = v0;
            *(float4*)&Bs[bkk][bc + 4] = v1;
        }
        __syncthreads();

#pragma unroll
        for (int kk = 0; kk < 16; ++kk) {
            float a[8], b[8];
            *(float4*)(a)     = *(const float4*)&As[kk][ty * 8];
            *(float4*)(a + 4) = *(const float4*)&As[kk][ty * 8 + 4];
            *(float4*)(b)     = *(const float4*)&Bs[kk][tx * 8];
            *(float4*)(b + 4) = *(const float4*)&Bs[kk][tx * 8 + 4];
#pragma unroll
            for (int i = 0; i < 8; ++i)
#pragma unroll
                for (int j = 0; j < 8; ++j)
                    acc[i][j] = fmaf(a[i], b[j], acc[i][j]);
        }
        __syncthreads();
    }

    // ---- epilogue
    float bb[8];
    if (HASBIAS) {
        *(float4*)(bb)     = *(const float4*)(bias + colBase + tx * 8);
        *(float4*)(bb + 4) = *(const float4*)(bias + colBase + tx * 8 + 4);
    }
#pragma unroll
    for (int i = 0; i < 8; ++i) {
        long long r = rowBase + ty * 8 + i;
        float* cp = C + r * N + colBase + tx * 8;
        float4 v0, v1;
        if (HASBIAS) {
            v0 = make_float4(acc[i][0] + bb[0], acc[i][1] + bb[1],
                             acc[i][2] + bb[2], acc[i][3] + bb[3]);
            v1 = make_float4(acc[i][4] + bb[4], acc[i][5] + bb[5],
                             acc[i][6] + bb[6], acc[i][7] + bb[7]);
        } else {
            v0 = make_float4(acc[i][0], acc[i][1], acc[i][2], acc[i][3]);
            v1 = make_float4(acc[i][4], acc[i][5], acc[i][6], acc[i][7]);
        }
        *(float4*)(cp)     = v0;
        *(float4*)(cp + 4) = v1;
    }
}

// ---------------------------------------------------------------------------
// Row softmax over 2048 columns, in place. One block (256 threads) per row;
// 8 elements per thread held in registers (single global read + write).
// ---------------------------------------------------------------------------
__global__ __launch_bounds__(256)
void softmax_rows_kernel(float* __restrict__ S)
{
    const int COLS = SEQ;
    __shared__ float red[8];

    float* p = S + (long long)blockIdx.x * COLS;
    const int tid = threadIdx.x;

    float v[8];
    float m = -1e30f;
#pragma unroll
    for (int u = 0; u < 8; ++u) {
        v[u] = p[tid + u * 256];
        m = fmaxf(m, v[u]);
    }
#pragma unroll
    for (int o = 16; o > 0; o >>= 1) m = fmaxf(m, __shfl_xor_sync(0xffffffffu, m, o));
    if ((tid & 31) == 0) red[tid >> 5] = m;
    __syncthreads();
    m = red[0];
#pragma unroll
    for (int w = 1; w < 8; ++w) m = fmaxf(m, red[w]);
    __syncthreads();

    float s = 0.0f;
#pragma unroll
    for (int u = 0; u < 8; ++u) {
        v[u] = __expf(v[u] - m);
        s += v[u];
    }
#pragma unroll
    for (int o = 16; o > 0; o >>= 1) s += __shfl_xor_sync(0xffffffffu, s, o);
    if ((tid & 31) == 0) red[tid >> 5] = s;
    __syncthreads();
    s = red[0];
#pragma unroll
    for (int w = 1; w < 8; ++w) s += red[w];

    const float inv = 1.0f / s;
#pragma unroll
    for (int u = 0; u < 8; ++u) p[tid + u * 256] = v[u] * inv;
}

// ---------------------------------------------------------------------------
extern "C" void kernel_launch(void* const* d_in, const int* in_sizes, int n_in,
                              void* d_out, int out_size)
{
    const float* x  = (const float*)d_in[0];
    const float* Wq = (const float*)d_in[1];
    const float* bq = (const float*)d_in[2];
    const float* Wk = (const float*)d_in[3];
    const float* bk = (const float*)d_in[4];
    const float* Wv = (const float*)d_in[5];
    const float* bv = (const float*)d_in[6];
    float* out = (float*)d_out;

    float *Q, *K, *V, *S;
    cudaGetSymbolAddress((void**)&Q, g_Q);
    cudaGetSymbolAddress((void**)&K, g_K);
    cudaGetSymbolAddress((void**)&V, g_V);
    cudaGetSymbolAddress((void**)&S, g_S);

    dim3 blk(256);

    // Projections: [16384,1024] = x[16384,1024] @ W[1024,1024] + b
    dim3 gp(DIM / 128, ROWS / 128, 1);
    gemm_kernel<false, true><<<gp, blk>>>(x, Wq, bq, Q, ROWS, DIM, DIM, 0, 0, 0);
    gemm_kernel<false, true><<<gp, blk>>>(x, Wk, bk, K, ROWS, DIM, DIM, 0, 0, 0);
    gemm_kernel<false, true><<<gp, blk>>>(x, Wv, bv, V, ROWS, DIM, DIM, 0, 0, 0);

    // Scores: S[b] = Q[b] @ K[b]^T  (M=N=2048, K=1024), batched over 8
    dim3 gs(SEQ / 128, SEQ / 128, BATCH);
    gemm_kernel<true, false><<<gs, blk>>>(Q, K, nullptr, S, SEQ, SEQ, DIM,
                                          (long long)SEQ * DIM,
                                          (long long)SEQ * DIM,
                                          (long long)SEQ * SEQ);

    // Softmax over last dim, in place
    softmax_rows_kernel<<<BATCH * SEQ, 256>>>(S);

    // Output: out[b] = P[b] @ V[b]  (M=2048, N=1024, K=2048), batched over 8
    dim3 ga(DIM / 128, SEQ / 128, BATCH);
    gemm_kernel<false, false><<<ga, blk>>>(S, V, nullptr, out, SEQ, DIM, SEQ,
                                           (long long)SEQ * SEQ,
                                           (long long)SEQ * DIM,
                                           (long long)SEQ * DIM);
}

// round 3
// speedup vs baseline: 2.5674x; 2.5674x over previous
#include <cuda_runtime.h>
#include <cuda_bf16.h>
#include <cstdint>

// Problem constants: B=8, N=2048, D=DQ=DV=1024
#define BATCH 8
#define SEQ   2048
#define DIM   1024
#define ROWS  (BATCH * SEQ)        // 16384

// ---------------------------------------------------------------------------
// Device scratch
// ---------------------------------------------------------------------------
__device__ __nv_bfloat16 g_xhi[(size_t)ROWS * DIM];
__device__ __nv_bfloat16 g_xlo[(size_t)ROWS * DIM];
__device__ __nv_bfloat16 g_Wqthi[(size_t)DIM * DIM], g_Wqtlo[(size_t)DIM * DIM];
__device__ __nv_bfloat16 g_Wkthi[(size_t)DIM * DIM], g_Wktlo[(size_t)DIM * DIM];
__device__ __nv_bfloat16 g_Wvthi[(size_t)DIM * DIM], g_Wvtlo[(size_t)DIM * DIM];
__device__ float g_Q[(size_t)ROWS * DIM];
__device__ float g_K[(size_t)ROWS * DIM];
__device__ float g_V[(size_t)ROWS * DIM];
__device__ __nv_bfloat16 g_Qhi[(size_t)ROWS * DIM], g_Qlo[(size_t)ROWS * DIM];
__device__ __nv_bfloat16 g_Khi[(size_t)ROWS * DIM], g_Klo[(size_t)ROWS * DIM];
__device__ __nv_bfloat16 g_Vthi[(size_t)BATCH * DIM * SEQ], g_Vtlo[(size_t)BATCH * DIM * SEQ];
__device__ float g_S[(size_t)BATCH * SEQ * SEQ];
__device__ __nv_bfloat16 g_Phi[(size_t)BATCH * SEQ * SEQ], g_Plo[(size_t)BATCH * SEQ * SEQ];

// ---------------------------------------------------------------------------
// PTX helpers (portable: mma.sync / ldmatrix / cp.async — all sm_80+)
// ---------------------------------------------------------------------------
__device__ __forceinline__ uint32_t smem_to_u32(const void* p) {
    uint32_t a;
    asm("{ .reg .u64 t; cvta.to.shared.u64 t, %1; cvt.u32.u64 %0, t; }" : "=r"(a) : "l"(p));
    return a;
}
__device__ __forceinline__ void cp16(uint32_t dst, const void* src) {
    asm volatile("cp.async.cg.shared.global [%0], [%1], 16;" :: "r"(dst), "l"(src));
}
#define CP_COMMIT() asm volatile("cp.async.commit_group;" ::: "memory")
#define CP_WAIT0()  asm volatile("cp.async.wait_group 0;" ::: "memory")

__device__ __forceinline__ void ldsm_x4(uint32_t* r, uint32_t addr) {
    asm volatile("ldmatrix.sync.aligned.m8n8.x4.shared.b16 {%0,%1,%2,%3}, [%4];"
        : "=r"(r[0]), "=r"(r[1]), "=r"(r[2]), "=r"(r[3]) : "r"(addr));
}
__device__ __forceinline__ void mma16816(float* d, const uint32_t* a, const uint32_t* b) {
    asm volatile("mma.sync.aligned.m16n8k16.row.col.f32.bf16.bf16.f32 "
        "{%0,%1,%2,%3}, {%4,%5,%6,%7}, {%8,%9}, {%0,%1,%2,%3};"
        : "+f"(d[0]), "+f"(d[1]), "+f"(d[2]), "+f"(d[3])
        : "r"(a[0]), "r"(a[1]), "r"(a[2]), "r"(a[3]), "r"(b[0]), "r"(b[1]));
}

// ---------------------------------------------------------------------------
// mma.sync GEMM: C[M,N](fp32) = sum_k A[m,k]*B[n,k], A,B split hi/lo bf16,
// both K-major. Block tile 128x128, K-chunk 32, 8 warps (4x2), warp 32x64.
// Smem rows padded to 40 bf16 (80 B) => 16B-aligned cp.async dst AND
// conflict-free ldmatrix (bank shift 20/row).
// ---------------------------------------------------------------------------
#define SPAD   40                        // bf16 elems per smem row
#define TILEB  (128 * SPAD * 2)          // 10240 B per tile
#define STAGEB (4 * TILEB)               // Ahi, Alo, Bhi, Blo
#define GEMM_SMEM (2 * STAGEB)           // double buffer: 81920 B

template<bool HASBIAS>
__global__ __launch_bounds__(256, 1)
void gemm_mma(const __nv_bfloat16* __restrict__ Ahi, const __nv_bfloat16* __restrict__ Alo,
              const __nv_bfloat16* __restrict__ Bhi, const __nv_bfloat16* __restrict__ Blo,
              const float* __restrict__ bias, float* __restrict__ C,
              int M, int N, int K,
              long long sA, long long sB, long long sC)
{
    extern __shared__ char smem[];
    const uint32_t sbase = smem_to_u32(smem);

    const int tid = threadIdx.x;
    const int wid = tid >> 5;
    const int lid = tid & 31;
    const int wm  = wid & 3;           // 0..3  (M)
    const int wn  = wid >> 2;          // 0..1  (N)
    const int rowBase = blockIdx.y * 128;
    const int colBase = blockIdx.x * 128;

    const __nv_bfloat16* As[2] = { Ahi + (long long)blockIdx.z * sA,
                                   Alo + (long long)blockIdx.z * sA };
    const __nv_bfloat16* Bs[2] = { Bhi + (long long)blockIdx.z * sB,
                                   Blo + (long long)blockIdx.z * sB };
    float* C_b = C + (long long)blockIdx.z * sC;

    // per-thread load mapping: 512 16B-segments per tile, 2 per thread
    const int seg0row = (tid * 2) >> 2, seg0c = (tid * 2) & 3;
    const int seg1row = (tid * 2 + 1) >> 2, seg1c = (tid * 2 + 1) & 3;

    auto load_chunk = [&](int c, int stage) {
        const uint32_t st = sbase + stage * STAGEB;
        const long long kOff = (long long)c * 32;
#pragma unroll
        for (int t = 0; t < 4; ++t) {
            const __nv_bfloat16* src = (t < 2) ? As[t] : Bs[t - 2];
            const int rB = (t < 2) ? rowBase : colBase;
            const uint32_t tb = st + t * TILEB;
            cp16(tb + seg0row * (SPAD * 2) + seg0c * 16,
                 src + (long long)(rB + seg0row) * K + kOff + seg0c * 8);
            cp16(tb + seg1row * (SPAD * 2) + seg1c * 16,
                 src + (long long)(rB + seg1row) * K + kOff + seg1c * 8);
        }
        CP_COMMIT();
    };

    float acc[2][8][4];
#pragma unroll
    for (int i = 0; i < 2; ++i)
#pragma unroll
        for (int j = 0; j < 8; ++j)
#pragma unroll
            for (int q = 0; q < 4; ++q) acc[i][j][q] = 0.0f;

    // ldmatrix lane address offsets (within a tile)
    // A frag (x4): row = mBase + (lane&15), kcol = (lane>>4)*8
    const uint32_t aRowOff = (uint32_t)(lid & 15) * (SPAD * 2) + (uint32_t)(lid >> 4) * 16;
    // B frag (x4, two n8 blocks): row = nBase + (lane&7) + ((lane>>4)&1)*8, kcol = ((lane>>3)&1)*8
    const uint32_t bRowOff = ((uint32_t)(lid & 7) + ((uint32_t)(lid >> 4) & 1) * 8) * (SPAD * 2)
                           + (((uint32_t)(lid >> 3) & 1)) * 16;

    const int nChunks = K >> 5;

    load_chunk(0, 0);

    for (int c = 0; c < nChunks; ++c) {
        const int s = c & 1;
        CP_WAIT0();
        __syncthreads();
        if (c + 1 < nChunks) load_chunk(c + 1, s ^ 1);

        const uint32_t st = sbase + s * STAGEB;
        const uint32_t aHiB = st + 0 * TILEB + (uint32_t)(wm * 32) * (SPAD * 2) + aRowOff;
        const uint32_t aLoB = st + 1 * TILEB + (uint32_t)(wm * 32) * (SPAD * 2) + aRowOff;
        const uint32_t bHiB = st + 2 * TILEB + (uint32_t)(wn * 64) * (SPAD * 2) + bRowOff;
        const uint32_t bLoB = st + 3 * TILEB + (uint32_t)(wn * 64) * (SPAD * 2) + bRowOff;

#pragma unroll
        for (int k16 = 0; k16 < 2; ++k16) {
            const uint32_t kb = (uint32_t)(k16 * 32);   // 16 bf16 = 32 B
            uint32_t ah[2][4], al[2][4];
            ldsm_x4(ah[0], aHiB + kb);
            ldsm_x4(ah[1], aHiB + kb + 16 * (SPAD * 2));
            ldsm_x4(al[0], aLoB + kb);
            ldsm_x4(al[1], aLoB + kb + 16 * (SPAD * 2));

            uint32_t bh[8][2], bl[8][2];
#pragma unroll
            for (int p = 0; p < 4; ++p) {
                uint32_t r[4];
                ldsm_x4(r, bHiB + kb + (uint32_t)(p * 16) * (SPAD * 2));
                bh[p * 2][0] = r[0]; bh[p * 2][1] = r[1];
                bh[p * 2 + 1][0] = r[2]; bh[p * 2 + 1][1] = r[3];
                ldsm_x4(r, bLoB + kb + (uint32_t)(p * 16) * (SPAD * 2));
                bl[p * 2][0] = r[0]; bl[p * 2][1] = r[1];
                bl[p * 2 + 1][0] = r[2]; bl[p * 2 + 1][1] = r[3];
            }

#pragma unroll
            for (int i = 0; i < 2; ++i)
#pragma unroll
                for (int j = 0; j < 8; ++j) {
                    mma16816(acc[i][j], ah[i], bh[j]);
                    mma16816(acc[i][j], ah[i], bl[j]);
                    mma16816(acc[i][j], al[i], bh[j]);
                }
        }
        __syncthreads();
    }

    // Epilogue: direct register -> gmem, fused bias
    const int g = lid >> 2, t = lid & 3;
#pragma unroll
    for (int i = 0; i < 2; ++i) {
        const int r0 = rowBase + wm * 32 + i * 16 + g;
        const int r1 = r0 + 8;
#pragma unroll
        for (int j = 0; j < 8; ++j) {
            const int col = colBase + wn * 64 + j * 8 + t * 2;
            float b0 = 0.f, b1 = 0.f;
            if (HASBIAS) { b0 = __ldg(bias + col); b1 = __ldg(bias + col + 1); }
            float2 v0 = make_float2(acc[i][j][0] + b0, acc[i][j][1] + b1);
            float2 v1 = make_float2(acc[i][j][2] + b0, acc[i][j][3] + b1);
            *(float2*)(C_b + (long long)r0 * N + col) = v0;
            *(float2*)(C_b + (long long)r1 * N + col) = v1;
        }
    }
}

// ---------------------------------------------------------------------------
// Split fp32 -> (hi, lo) bf16
// ---------------------------------------------------------------------------
__global__ __launch_bounds__(256)
void split_kernel(const float4* __restrict__ in, uint2* __restrict__ hi, uint2* __restrict__ lo,
                  long long n4)
{
    long long i = (long long)blockIdx.x * 256 + threadIdx.x;
    if (i >= n4) return;
    float4 v = in[i];
    __nv_bfloat16 hx = __float2bfloat16(v.x);
    __nv_bfloat16 hy = __float2bfloat16(v.y);
    __nv_bfloat16 hz = __float2bfloat16(v.z);
    __nv_bfloat16 hw = __float2bfloat16(v.w);
    __nv_bfloat16 lx = __float2bfloat16(v.x - __bfloat162float(hx));
    __nv_bfloat16 ly = __float2bfloat16(v.y - __bfloat162float(hy));
    __nv_bfloat16 lz = __float2bfloat16(v.z - __bfloat162float(hz));
    __nv_bfloat16 lw = __float2bfloat16(v.w - __bfloat162float(hw));
    __nv_bfloat162 h01, h23, l01, l23;
    h01.x = hx; h01.y = hy; h23.x = hz; h23.y = hw;
    l01.x = lx; l01.y = ly; l23.x = lz; l23.y = lw;
    uint2 ho, lo2;
    ho.x = *(uint32_t*)&h01; ho.y = *(uint32_t*)&h23;
    lo2.x = *(uint32_t*)&l01; lo2.y = *(uint32_t*)&l23;
    hi[i] = ho;
    lo[i] = lo2;
}

// ---------------------------------------------------------------------------
// Transpose fp32 [R,C] -> bf16 hi/lo [C,R], batched via blockIdx.z.
// ---------------------------------------------------------------------------
__global__ __launch_bounds__(256)
void transpose_split_kernel(const float* __restrict__ in,
                            __nv_bfloat16* __restrict__ hi, __nv_bfloat16* __restrict__ lo,
                            int R, int C, long long sIn, long long sOut)
{
    __shared__ float t[32][33];
    const float* inb = in + (long long)blockIdx.z * sIn;
    __nv_bfloat16* hib = hi + (long long)blockIdx.z * sOut;
    __nv_bfloat16* lob = lo + (long long)blockIdx.z * sOut;

    const int tx = threadIdx.x, ty = threadIdx.y;
    const int x = blockIdx.x * 32 + tx;
    const int y0 = blockIdx.y * 32;
#pragma unroll
    for (int j = 0; j < 4; ++j)
        t[ty + j * 8][tx] = inb[(long long)(y0 + ty + j * 8) * C + x];
    __syncthreads();

    const int ox = blockIdx.y * 32 + tx;
    const int oy0 = blockIdx.x * 32;
#pragma unroll
    for (int j = 0; j < 4; ++j) {
        float v = t[tx][ty + j * 8];
        __nv_bfloat16 h = __float2bfloat16(v);
        __nv_bfloat16 l = __float2bfloat16(v - __bfloat162float(h));
        long long o = (long long)(oy0 + ty + j * 8) * R + ox;
        hib[o] = h;
        lob[o] = l;
    }
}

// ---------------------------------------------------------------------------
// Row softmax over 2048 columns, in place.
// ---------------------------------------------------------------------------
__global__ __launch_bounds__(256)
void softmax_rows_kernel(float* __restrict__ S)
{
    __shared__ float red[8];
    float* p = S + (long long)blockIdx.x * SEQ;
    const int tid = threadIdx.x;

    float v[8];
    float m = -1e30f;
#pragma unroll
    for (int u = 0; u < 8; ++u) {
        v[u] = p[tid + u * 256];
        m = fmaxf(m, v[u]);
    }
#pragma unroll
    for (int o = 16; o > 0; o >>= 1) m = fmaxf(m, __shfl_xor_sync(0xffffffffu, m, o));
    if ((tid & 31) == 0) red[tid >> 5] = m;
    __syncthreads();
    m = red[0];
#pragma unroll
    for (int w = 1; w < 8; ++w) m = fmaxf(m, red[w]);
    __syncthreads();

    float s = 0.0f;
#pragma unroll
    for (int u = 0; u < 8; ++u) {
        v[u] = __expf(v[u] - m);
        s += v[u];
    }
#pragma unroll
    for (int o = 16; o > 0; o >>= 1) s += __shfl_xor_sync(0xffffffffu, s, o);
    if ((tid & 31) == 0) red[tid >> 5] = s;
    __syncthreads();
    s = red[0];
#pragma unroll
    for (int w = 1; w < 8; ++w) s += red[w];

    const float inv = 1.0f / s;
#pragma unroll
    for (int u = 0; u < 8; ++u) p[tid + u * 256] = v[u] * inv;
}

// ---------------------------------------------------------------------------
extern "C" void kernel_launch(void* const* d_in, const int* in_sizes, int n_in,
                              void* d_out, int out_size)
{
    const float* x  = (const float*)d_in[0];
    const float* Wq = (const float*)d_in[1];
    const float* bq = (const float*)d_in[2];
    const float* Wk = (const float*)d_in[3];
    const float* bk = (const float*)d_in[4];
    const float* Wv = (const float*)d_in[5];
    const float* bv = (const float*)d_in[6];
    float* out = (float*)d_out;

    __nv_bfloat16 *xhi, *xlo, *Wqthi, *Wqtlo, *Wkthi, *Wktlo, *Wvthi, *Wvtlo;
    __nv_bfloat16 *Qhi, *Qlo, *Khi, *Klo, *Vthi, *Vtlo, *Phi, *Plo;
    float *Q, *K, *V, *S;
    cudaGetSymbolAddress((void**)&xhi, g_xhi);     cudaGetSymbolAddress((void**)&xlo, g_xlo);
    cudaGetSymbolAddress((void**)&Wqthi, g_Wqthi); cudaGetSymbolAddress((void**)&Wqtlo, g_Wqtlo);
    cudaGetSymbolAddress((void**)&Wkthi, g_Wkthi); cudaGetSymbolAddress((void**)&Wktlo, g_Wktlo);
    cudaGetSymbolAddress((void**)&Wvthi, g_Wvthi); cudaGetSymbolAddress((void**)&Wvtlo, g_Wvtlo);
    cudaGetSymbolAddress((void**)&Q, g_Q);   cudaGetSymbolAddress((void**)&K, g_K);
    cudaGetSymbolAddress((void**)&V, g_V);   cudaGetSymbolAddress((void**)&S, g_S);
    cudaGetSymbolAddress((void**)&Qhi, g_Qhi); cudaGetSymbolAddress((void**)&Qlo, g_Qlo);
    cudaGetSymbolAddress((void**)&Khi, g_Khi); cudaGetSymbolAddress((void**)&Klo, g_Klo);
    cudaGetSymbolAddress((void**)&Vthi, g_Vthi); cudaGetSymbolAddress((void**)&Vtlo, g_Vtlo);
    cudaGetSymbolAddress((void**)&Phi, g_Phi); cudaGetSymbolAddress((void**)&Plo, g_Plo);

    cudaFuncSetAttribute(gemm_mma<true>,  cudaFuncAttributeMaxDynamicSharedMemorySize, GEMM_SMEM);
    cudaFuncSetAttribute(gemm_mma<false>, cudaFuncAttributeMaxDynamicSharedMemorySize, GEMM_SMEM);

    dim3 tblk(32, 8);

    // 1) Split x
    {
        long long n4 = (long long)ROWS * DIM / 4;
        split_kernel<<<(unsigned)((n4 + 255) / 256), 256>>>((const float4*)x, (uint2*)xhi, (uint2*)xlo, n4);
    }
    // 2) Transpose+split weights: W[D,DQ] -> Wt[DQ,D]
    transpose_split_kernel<<<dim3(DIM / 32, DIM / 32, 1), tblk>>>(Wq, Wqthi, Wqtlo, DIM, DIM, 0, 0);
    transpose_split_kernel<<<dim3(DIM / 32, DIM / 32, 1), tblk>>>(Wk, Wkthi, Wktlo, DIM, DIM, 0, 0);
    transpose_split_kernel<<<dim3(DIM / 32, DIM / 32, 1), tblk>>>(Wv, Wvthi, Wvtlo, DIM, DIM, 0, 0);

    // 3) Projections: [16384,1024] x [1024,1024] + bias
    {
        dim3 g(DIM / 128, ROWS / 128, 1);
        gemm_mma<true><<<g, 256, GEMM_SMEM>>>(xhi, xlo, Wqthi, Wqtlo, bq, Q, ROWS, DIM, DIM, 0, 0, 0);
        gemm_mma<true><<<g, 256, GEMM_SMEM>>>(xhi, xlo, Wkthi, Wktlo, bk, K, ROWS, DIM, DIM, 0, 0, 0);
        gemm_mma<true><<<g, 256, GEMM_SMEM>>>(xhi, xlo, Wvthi, Wvtlo, bv, V, ROWS, DIM, DIM, 0, 0, 0);
    }
    // 4) Split Q, K; transpose+split V per batch
    {
        long long n4 = (long long)ROWS * DIM / 4;
        split_kernel<<<(unsigned)((n4 + 255) / 256), 256>>>((const float4*)Q, (uint2*)Qhi, (uint2*)Qlo, n4);
        split_kernel<<<(unsigned)((n4 + 255) / 256), 256>>>((const float4*)K, (uint2*)Khi, (uint2*)Klo, n4);
        transpose_split_kernel<<<dim3(DIM / 32, SEQ / 32, BATCH), tblk>>>(
            V, Vthi, Vtlo, SEQ, DIM, (long long)SEQ * DIM, (long long)DIM * SEQ);
    }
    // 5) Scores: S[b] = Q[b] @ K[b]^T
    {
        dim3 g(SEQ / 128, SEQ / 128, BATCH);
        gemm_mma<false><<<g, 256, GEMM_SMEM>>>(Qhi, Qlo, Khi, Klo, nullptr, S, SEQ, SEQ, DIM,
                                               (long long)SEQ * DIM, (long long)SEQ * DIM,
                                               (long long)SEQ * SEQ);
    }
    // 6) Softmax
    softmax_rows_kernel<<<BATCH * SEQ, 256>>>(S);
    // 7) Split P
    {
        long long n4 = (long long)BATCH * SEQ * SEQ / 4;
        split_kernel<<<(unsigned)((n4 + 255) / 256), 256>>>((const float4*)S, (uint2*)Phi, (uint2*)Plo, n4);
    }
    // 8) Out: out[b] = P[b] @ V[b]
    {
        dim3 g(DIM / 128, SEQ / 128, BATCH);
        gemm_mma<false><<<g, 256, GEMM_SMEM>>>(Phi, Plo, Vthi, Vtlo, nullptr, out, SEQ, DIM, SEQ,
                                               (long long)SEQ * SEQ, (long long)DIM * SEQ,
                                               (long long)SEQ * DIM);
    }
}

// round 4
// speedup vs baseline: 2.5844x; 1.0066x over previous
#include <cuda_runtime.h>
#include <cuda_bf16.h>
#include <cstdint>

// Problem constants: B=8, N=2048, D=DQ=DV=1024
#define BATCH 8
#define SEQ   2048
#define DIM   1024
#define ROWS  (BATCH * SEQ)        // 16384

// ---------------------------------------------------------------------------
// Device scratch
// ---------------------------------------------------------------------------
__device__ __nv_bfloat16 g_xhi[(size_t)ROWS * DIM];
__device__ __nv_bfloat16 g_xlo[(size_t)ROWS * DIM];
__device__ __nv_bfloat16 g_Wqthi[(size_t)DIM * DIM], g_Wqtlo[(size_t)DIM * DIM];
__device__ __nv_bfloat16 g_Wkthi[(size_t)DIM * DIM], g_Wktlo[(size_t)DIM * DIM];
__device__ __nv_bfloat16 g_Wvthi[(size_t)DIM * DIM], g_Wvtlo[(size_t)DIM * DIM];
__device__ __nv_bfloat16 g_Qhi[(size_t)ROWS * DIM], g_Qlo[(size_t)ROWS * DIM];
__device__ __nv_bfloat16 g_Khi[(size_t)ROWS * DIM], g_Klo[(size_t)ROWS * DIM];
__device__ __nv_bfloat16 g_Vthi[(size_t)BATCH * DIM * SEQ], g_Vtlo[(size_t)BATCH * DIM * SEQ];
__device__ float g_S[(size_t)BATCH * SEQ * SEQ];
__device__ __nv_bfloat16 g_Phi[(size_t)BATCH * SEQ * SEQ], g_Plo[(size_t)BATCH * SEQ * SEQ];

// ---------------------------------------------------------------------------
// PTX helpers (portable sm_80+: mma.sync / ldmatrix / cp.async)
// ---------------------------------------------------------------------------
__device__ __forceinline__ uint32_t smem_to_u32(const void* p) {
    uint32_t a;
    asm("{ .reg .u64 t; cvta.to.shared.u64 t, %1; cvt.u32.u64 %0, t; }" : "=r"(a) : "l"(p));
    return a;
}
__device__ __forceinline__ void cp16(uint32_t dst, const void* src) {
    asm volatile("cp.async.cg.shared.global [%0], [%1], 16;" :: "r"(dst), "l"(src));
}
#define CP_COMMIT() asm volatile("cp.async.commit_group;" ::: "memory")
#define CP_WAIT0()  asm volatile("cp.async.wait_group 0;" ::: "memory")

__device__ __forceinline__ void ldsm_x4(uint32_t* r, uint32_t addr) {
    asm volatile("ldmatrix.sync.aligned.m8n8.x4.shared.b16 {%0,%1,%2,%3}, [%4];"
        : "=r"(r[0]), "=r"(r[1]), "=r"(r[2]), "=r"(r[3]) : "r"(addr));
}
__device__ __forceinline__ void mma16816(float* d, const uint32_t* a, const uint32_t* b) {
    asm volatile("mma.sync.aligned.m16n8k16.row.col.f32.bf16.bf16.f32 "
        "{%0,%1,%2,%3}, {%4,%5,%6,%7}, {%8,%9}, {%0,%1,%2,%3};"
        : "+f"(d[0]), "+f"(d[1]), "+f"(d[2]), "+f"(d[3])
        : "r"(a[0]), "r"(a[1]), "r"(a[2]), "r"(a[3]), "r"(b[0]), "r"(b[1]));
}
// split fp32 pair -> packed bf16x2 hi and lo
__device__ __forceinline__ void split2(float a, float b, uint32_t& hi2, uint32_t& lo2) {
    __nv_bfloat16 ha = __float2bfloat16(a);
    __nv_bfloat16 hb = __float2bfloat16(b);
    __nv_bfloat16 la = __float2bfloat16(a - __bfloat162float(ha));
    __nv_bfloat16 lb = __float2bfloat16(b - __bfloat162float(hb));
    __nv_bfloat162 h; h.x = ha; h.y = hb;
    __nv_bfloat162 l; l.x = la; l.y = lb;
    hi2 = *(uint32_t*)&h;
    lo2 = *(uint32_t*)&l;
}

// ---------------------------------------------------------------------------
// mma.sync GEMM: 128x128 block tile, K-chunk 32, 8 warps (4x2), warp 32x64.
// A,B hi/lo bf16, K-major. Smem rows padded to 40 bf16 (80 B).
// EPI: 0 = fp32 out (+bias), 1 = split hi/lo bf16 out (+bias),
//      2 = split hi/lo bf16 TRANSPOSED out (V^T), smem-staged (+bias).
// ---------------------------------------------------------------------------
#define SPAD   40
#define TILEB  (128 * SPAD * 2)          // 10240 B
#define STAGEB (4 * TILEB)               // 40960 B
#define GEMM_SMEM (2 * STAGEB)           // 81920 B

template<int EPI, bool HASBIAS>
__global__ __launch_bounds__(256, 2)
void gemm_mma(const __nv_bfloat16* __restrict__ Ahi, const __nv_bfloat16* __restrict__ Alo,
              const __nv_bfloat16* __restrict__ Bhi, const __nv_bfloat16* __restrict__ Blo,
              const float* __restrict__ bias,
              float* __restrict__ Cf,
              __nv_bfloat16* __restrict__ Chi, __nv_bfloat16* __restrict__ Clo,
              int M, int N, int K,
              long long sA, long long sB, long long sC)
{
    extern __shared__ char smem[];
    const uint32_t sbase = smem_to_u32(smem);

    const int tid = threadIdx.x;
    const int wid = tid >> 5;
    const int lid = tid & 31;
    const int wm  = wid & 3;
    const int wn  = wid >> 2;
    const int rowBase = blockIdx.y * 128;
    const int colBase = blockIdx.x * 128;

    const __nv_bfloat16* As[2] = { Ahi + (long long)blockIdx.z * sA,
                                   Alo + (long long)blockIdx.z * sA };
    const __nv_bfloat16* Bs[2] = { Bhi + (long long)blockIdx.z * sB,
                                   Blo + (long long)blockIdx.z * sB };

    const int seg0row = (tid * 2) >> 2, seg0c = (tid * 2) & 3;
    const int seg1row = (tid * 2 + 1) >> 2, seg1c = (tid * 2 + 1) & 3;

    auto load_chunk = [&](int c, int stage) {
        const uint32_t st = sbase + stage * STAGEB;
        const long long kOff = (long long)c * 32;
#pragma unroll
        for (int t = 0; t < 4; ++t) {
            const __nv_bfloat16* src = (t < 2) ? As[t] : Bs[t - 2];
            const int rB = (t < 2) ? rowBase : colBase;
            const uint32_t tb = st + t * TILEB;
            cp16(tb + seg0row * (SPAD * 2) + seg0c * 16,
                 src + (long long)(rB + seg0row) * K + kOff + seg0c * 8);
            cp16(tb + seg1row * (SPAD * 2) + seg1c * 16,
                 src + (long long)(rB + seg1row) * K + kOff + seg1c * 8);
        }
        CP_COMMIT();
    };

    float acc[2][8][4];
#pragma unroll
    for (int i = 0; i < 2; ++i)
#pragma unroll
        for (int j = 0; j < 8; ++j)
#pragma unroll
            for (int q = 0; q < 4; ++q) acc[i][j][q] = 0.0f;

    const uint32_t aRowOff = (uint32_t)(lid & 15) * (SPAD * 2) + (uint32_t)(lid >> 4) * 16;
    const uint32_t bRowOff = ((uint32_t)(lid & 7) + ((uint32_t)(lid >> 4) & 1) * 8) * (SPAD * 2)
                           + (((uint32_t)(lid >> 3) & 1)) * 16;

    const int nChunks = K >> 5;
    load_chunk(0, 0);

    for (int c = 0; c < nChunks; ++c) {
        const int s = c & 1;
        CP_WAIT0();
        __syncthreads();
        if (c + 1 < nChunks) load_chunk(c + 1, s ^ 1);

        const uint32_t st = sbase + s * STAGEB;
        const uint32_t aHiB = st + 0 * TILEB + (uint32_t)(wm * 32) * (SPAD * 2) + aRowOff;
        const uint32_t aLoB = st + 1 * TILEB + (uint32_t)(wm * 32) * (SPAD * 2) + aRowOff;
        const uint32_t bHiB = st + 2 * TILEB + (uint32_t)(wn * 64) * (SPAD * 2) + bRowOff;
        const uint32_t bLoB = st + 3 * TILEB + (uint32_t)(wn * 64) * (SPAD * 2) + bRowOff;

#pragma unroll
        for (int k16 = 0; k16 < 2; ++k16) {
            const uint32_t kb = (uint32_t)(k16 * 32);
            uint32_t ah[2][4], al[2][4];
            ldsm_x4(ah[0], aHiB + kb);
            ldsm_x4(ah[1], aHiB + kb + 16 * (SPAD * 2));
            ldsm_x4(al[0], aLoB + kb);
            ldsm_x4(al[1], aLoB + kb + 16 * (SPAD * 2));
#pragma unroll
            for (int p = 0; p < 4; ++p) {
                uint32_t rh[4], rl[4];
                ldsm_x4(rh, bHiB + kb + (uint32_t)(p * 16) * (SPAD * 2));
                ldsm_x4(rl, bLoB + kb + (uint32_t)(p * 16) * (SPAD * 2));
                uint32_t bh0[2] = { rh[0], rh[1] }, bh1[2] = { rh[2], rh[3] };
                uint32_t bl0[2] = { rl[0], rl[1] }, bl1[2] = { rl[2], rl[3] };
#pragma unroll
                for (int i = 0; i < 2; ++i) {
                    mma16816(acc[i][p * 2],     ah[i], bh0);
                    mma16816(acc[i][p * 2],     ah[i], bl0);
                    mma16816(acc[i][p * 2],     al[i], bh0);
                    mma16816(acc[i][p * 2 + 1], ah[i], bh1);
                    mma16816(acc[i][p * 2 + 1], ah[i], bl1);
                    mma16816(acc[i][p * 2 + 1], al[i], bh1);
                }
            }
        }
        __syncthreads();
    }

    // ---------------- epilogues ----------------
    const int g = lid >> 2, t = lid & 3;

    if (EPI == 0) {
        float* C_b = Cf + (long long)blockIdx.z * sC;
#pragma unroll
        for (int i = 0; i < 2; ++i) {
            const int r0 = rowBase + wm * 32 + i * 16 + g;
            const int r1 = r0 + 8;
#pragma unroll
            for (int j = 0; j < 8; ++j) {
                const int col = colBase + wn * 64 + j * 8 + t * 2;
                float b0 = 0.f, b1 = 0.f;
                if (HASBIAS) { b0 = __ldg(bias + col); b1 = __ldg(bias + col + 1); }
                *(float2*)(C_b + (long long)r0 * N + col) =
                    make_float2(acc[i][j][0] + b0, acc[i][j][1] + b1);
                *(float2*)(C_b + (long long)r1 * N + col) =
                    make_float2(acc[i][j][2] + b0, acc[i][j][3] + b1);
            }
        }
    } else if (EPI == 1) {
        // direct split hi/lo bf16 output (row-major [M,N])
#pragma unroll
        for (int i = 0; i < 2; ++i) {
            const int r0 = rowBase + wm * 32 + i * 16 + g;
            const int r1 = r0 + 8;
#pragma unroll
            for (int j = 0; j < 8; ++j) {
                const int col = colBase + wn * 64 + j * 8 + t * 2;
                float b0 = 0.f, b1 = 0.f;
                if (HASBIAS) { b0 = __ldg(bias + col); b1 = __ldg(bias + col + 1); }
                uint32_t h2, l2;
                split2(acc[i][j][0] + b0, acc[i][j][1] + b1, h2, l2);
                *(uint32_t*)(Chi + (long long)r0 * N + col) = h2;
                *(uint32_t*)(Clo + (long long)r0 * N + col) = l2;
                split2(acc[i][j][2] + b0, acc[i][j][3] + b1, h2, l2);
                *(uint32_t*)(Chi + (long long)r1 * N + col) = h2;
                *(uint32_t*)(Clo + (long long)r1 * N + col) = l2;
            }
        }
    } else {
        // EPI == 2: transposed split output Vt[DIM, SEQ] per batch.
        // Stage fp32 tile (rows = seq-local, cols = dim-local) in smem.
        float* buf = (float*)smem;
#pragma unroll
        for (int i = 0; i < 2; ++i) {
            const int lr = wm * 32 + i * 16 + g;
#pragma unroll
            for (int j = 0; j < 8; ++j) {
                const int lc = wn * 64 + j * 8 + t * 2;
                float b0 = 0.f, b1 = 0.f;
                if (HASBIAS) {
                    b0 = __ldg(bias + colBase + lc);
                    b1 = __ldg(bias + colBase + lc + 1);
                }
                buf[lr * 129 + lc]           = acc[i][j][0] + b0;
                buf[lr * 129 + lc + 1]       = acc[i][j][1] + b1;
                buf[(lr + 8) * 129 + lc]     = acc[i][j][2] + b0;
                buf[(lr + 8) * 129 + lc + 1] = acc[i][j][3] + b1;
            }
        }
        __syncthreads();
        const int dcol = tid >> 1;                 // 0..127
        const int sb2  = (tid & 1) * 64;           // seq-local half
        const int bIdx = rowBase >> 11;            // batch
        const int srow0 = rowBase & (SEQ - 1);
        long long o = (long long)bIdx * DIM * SEQ + (long long)(colBase + dcol) * SEQ
                    + srow0 + sb2;
        __nv_bfloat16* Hb = Chi + o;
        __nv_bfloat16* Lb = Clo + o;
#pragma unroll
        for (int s2 = 0; s2 < 64; s2 += 2) {
            float v0 = buf[(sb2 + s2) * 129 + dcol];
            float v1 = buf[(sb2 + s2 + 1) * 129 + dcol];
            uint32_t h2, l2;
            split2(v0, v1, h2, l2);
            *(uint32_t*)(Hb + s2) = h2;
            *(uint32_t*)(Lb + s2) = l2;
        }
    }
}

// ---------------------------------------------------------------------------
// Split fp32 -> (hi, lo) bf16 (used for x only)
// ---------------------------------------------------------------------------
__global__ __launch_bounds__(256)
void split_kernel(const float4* __restrict__ in, uint2* __restrict__ hi, uint2* __restrict__ lo,
                  long long n4)
{
    long long i = (long long)blockIdx.x * 256 + threadIdx.x;
    if (i >= n4) return;
    float4 v = in[i];
    uint32_t h01, l01, h23, l23;
    split2(v.x, v.y, h01, l01);
    split2(v.z, v.w, h23, l23);
    uint2 ho, lo2;
    ho.x = h01; ho.y = h23;
    lo2.x = l01; lo2.y = l23;
    hi[i] = ho;
    lo[i] = lo2;
}

// ---------------------------------------------------------------------------
// Transpose fp32 [R,C] -> bf16 hi/lo [C,R] (weights)
// ---------------------------------------------------------------------------
__global__ __launch_bounds__(256)
void transpose_split_kernel(const float* __restrict__ in,
                            __nv_bfloat16* __restrict__ hi, __nv_bfloat16* __restrict__ lo,
                            int R, int C)
{
    __shared__ float t[32][33];
    const int tx = threadIdx.x, ty = threadIdx.y;
    const int x = blockIdx.x * 32 + tx;
    const int y0 = blockIdx.y * 32;
#pragma unroll
    for (int j = 0; j < 4; ++j)
        t[ty + j * 8][tx] = in[(long long)(y0 + ty + j * 8) * C + x];
    __syncthreads();

    const int ox = blockIdx.y * 32 + tx;
    const int oy0 = blockIdx.x * 32;
#pragma unroll
    for (int j = 0; j < 4; ++j) {
        float v = t[tx][ty + j * 8];
        __nv_bfloat16 h = __float2bfloat16(v);
        __nv_bfloat16 l = __float2bfloat16(v - __bfloat162float(h));
        long long o = (long long)(oy0 + ty + j * 8) * R + ox;
        hi[o] = h;
        lo[o] = l;
    }
}

// ---------------------------------------------------------------------------
// Fused softmax + split: reads S row (fp32), writes Phi/Plo rows (bf16).
// One block (256 threads) per row; thread handles 8 contiguous elements.
// ---------------------------------------------------------------------------
__global__ __launch_bounds__(256)
void softmax_split_kernel(const float* __restrict__ S,
                          __nv_bfloat16* __restrict__ Phi, __nv_bfloat16* __restrict__ Plo)
{
    __shared__ float red[8];
    const float* p = S + (long long)blockIdx.x * SEQ;
    const int tid = threadIdx.x;

    float v[8];
    *(float4*)(v)     = *(const float4*)(p + tid * 8);
    *(float4*)(v + 4) = *(const float4*)(p + tid * 8 + 4);

    float m = -1e30f;
#pragma unroll
    for (int u = 0; u < 8; ++u) m = fmaxf(m, v[u]);
#pragma unroll
    for (int o = 16; o > 0; o >>= 1) m = fmaxf(m, __shfl_xor_sync(0xffffffffu, m, o));
    if ((tid & 31) == 0) red[tid >> 5] = m;
    __syncthreads();
    m = red[0];
#pragma unroll
    for (int w = 1; w < 8; ++w) m = fmaxf(m, red[w]);
    __syncthreads();

    float s = 0.0f;
#pragma unroll
    for (int u = 0; u < 8; ++u) {
        v[u] = __expf(v[u] - m);
        s += v[u];
    }
#pragma unroll
    for (int o = 16; o > 0; o >>= 1) s += __shfl_xor_sync(0xffffffffu, s, o);
    if ((tid & 31) == 0) red[tid >> 5] = s;
    __syncthreads();
    s = red[0];
#pragma unroll
    for (int w = 1; w < 8; ++w) s += red[w];

    const float inv = 1.0f / s;
    uint4 ho, lo4;
    uint32_t* hp = (uint32_t*)&ho;
    uint32_t* lp = (uint32_t*)&lo4;
#pragma unroll
    for (int u = 0; u < 4; ++u)
        split2(v[u * 2] * inv, v[u * 2 + 1] * inv, hp[u], lp[u]);
    *(uint4*)(Phi + (long long)blockIdx.x * SEQ + tid * 8) = ho;
    *(uint4*)(Plo + (long long)blockIdx.x * SEQ + tid * 8) = lo4;
}

// ---------------------------------------------------------------------------
extern "C" void kernel_launch(void* const* d_in, const int* in_sizes, int n_in,
                              void* d_out, int out_size)
{
    const float* x  = (const float*)d_in[0];
    const float* Wq = (const float*)d_in[1];
    const float* bq = (const float*)d_in[2];
    const float* Wk = (const float*)d_in[3];
    const float* bk = (const float*)d_in[4];
    const float* Wv = (const float*)d_in[5];
    const float* bv = (const float*)d_in[6];
    float* out = (float*)d_out;

    __nv_bfloat16 *xhi, *xlo, *Wqthi, *Wqtlo, *Wkthi, *Wktlo, *Wvthi, *Wvtlo;
    __nv_bfloat16 *Qhi, *Qlo, *Khi, *Klo, *Vthi, *Vtlo, *Phi, *Plo;
    float *S;
    cudaGetSymbolAddress((void**)&xhi, g_xhi);     cudaGetSymbolAddress((void**)&xlo, g_xlo);
    cudaGetSymbolAddress((void**)&Wqthi, g_Wqthi); cudaGetSymbolAddress((void**)&Wqtlo, g_Wqtlo);
    cudaGetSymbolAddress((void**)&Wkthi, g_Wkthi); cudaGetSymbolAddress((void**)&Wktlo, g_Wktlo);
    cudaGetSymbolAddress((void**)&Wvthi, g_Wvthi); cudaGetSymbolAddress((void**)&Wvtlo, g_Wvtlo);
    cudaGetSymbolAddress((void**)&S, g_S);
    cudaGetSymbolAddress((void**)&Qhi, g_Qhi); cudaGetSymbolAddress((void**)&Qlo, g_Qlo);
    cudaGetSymbolAddress((void**)&Khi, g_Khi); cudaGetSymbolAddress((void**)&Klo, g_Klo);
    cudaGetSymbolAddress((void**)&Vthi, g_Vthi); cudaGetSymbolAddress((void**)&Vtlo, g_Vtlo);
    cudaGetSymbolAddress((void**)&Phi, g_Phi); cudaGetSymbolAddress((void**)&Plo, g_Plo);

    cudaFuncSetAttribute(gemm_mma<0, false>, cudaFuncAttributeMaxDynamicSharedMemorySize, GEMM_SMEM);
    cudaFuncSetAttribute(gemm_mma<1, true>,  cudaFuncAttributeMaxDynamicSharedMemorySize, GEMM_SMEM);
    cudaFuncSetAttribute(gemm_mma<2, true>,  cudaFuncAttributeMaxDynamicSharedMemorySize, GEMM_SMEM);

    dim3 tblk(32, 8);

    // 1) Split x
    {
        long long n4 = (long long)ROWS * DIM / 4;
        split_kernel<<<(unsigned)((n4 + 255) / 256), 256>>>((const float4*)x, (uint2*)xhi, (uint2*)xlo, n4);
    }
    // 2) Transpose+split weights: W[D,DQ] -> Wt[DQ,D]
    transpose_split_kernel<<<dim3(DIM / 32, DIM / 32), tblk>>>(Wq, Wqthi, Wqtlo, DIM, DIM);
    transpose_split_kernel<<<dim3(DIM / 32, DIM / 32), tblk>>>(Wk, Wkthi, Wktlo, DIM, DIM);
    transpose_split_kernel<<<dim3(DIM / 32, DIM / 32), tblk>>>(Wv, Wvthi, Wvtlo, DIM, DIM);

    // 3) Projections with fused split epilogues
    {
        dim3 g(DIM / 128, ROWS / 128, 1);
        gemm_mma<1, true><<<g, 256, GEMM_SMEM>>>(xhi, xlo, Wqthi, Wqtlo, bq,
                                                 nullptr, Qhi, Qlo, ROWS, DIM, DIM, 0, 0, 0);
        gemm_mma<1, true><<<g, 256, GEMM_SMEM>>>(xhi, xlo, Wkthi, Wktlo, bk,
                                                 nullptr, Khi, Klo, ROWS, DIM, DIM, 0, 0, 0);
        gemm_mma<2, true><<<g, 256, GEMM_SMEM>>>(xhi, xlo, Wvthi, Wvtlo, bv,
                                                 nullptr, Vthi, Vtlo, ROWS, DIM, DIM, 0, 0, 0);
    }
    // 4) Scores: S[b] = Q[b] @ K[b]^T
    {
        dim3 g(SEQ / 128, SEQ / 128, BATCH);
        gemm_mma<0, false><<<g, 256, GEMM_SMEM>>>(Qhi, Qlo, Khi, Klo, nullptr,
                                                  S, nullptr, nullptr, SEQ, SEQ, DIM,
                                                  (long long)SEQ * DIM, (long long)SEQ * DIM,
                                                  (long long)SEQ * SEQ);
    }
    // 5) Fused softmax + split -> Phi/Plo
    softmax_split_kernel<<<BATCH * SEQ, 256>>>(S, Phi, Plo);
    // 6) Out: out[b] = P[b] @ V[b]
    {
        dim3 g(DIM / 128, SEQ / 128, BATCH);
        gemm_mma<0, false><<<g, 256, GEMM_SMEM>>>(Phi, Plo, Vthi, Vtlo, nullptr,
                                                  out, nullptr, nullptr, SEQ, DIM, SEQ,
                                                  (long long)SEQ * SEQ, (long long)DIM * SEQ,
                                                  (long long)SEQ * DIM);
    }
}